// round 12
// baseline (speedup 1.0000x reference)
#include <cuda_runtime.h>
#include <math.h>

#define H_    192
#define W_    320
#define HW_   (H_*W_)
#define EPS_  1e-5f
#define INVD  (1.0f/507.0f)

#define HB     16               // output rows per CTA
#define NHB    12               // 192/16
#define NDH    8                // d's per half
#define NDCTA  16               // d's per CTA
#define GRIDX  20               // 20*16 = 320 d values, zero waste
#define NT     640              // threads: (half, x)
#define NSTEP  28               // HB+12 row steps
#define NSLOT  15               // circular R-row window (float4 rows)
#define PLW    344              // V plane width: 6+320+12(gap)+6

// ---------------- device scratch ----------------
__device__ float4 g_L4[HW_];                  // packed (l0,l1,l2,0)
__device__ float4 g_R4[HW_];                  // packed (r0,r1,r2,0)
__device__ float  g_hL[HW_];                  // horiz 13-tap sum of L (3ch)
__device__ float  g_hR1[HW_];                 // of R
__device__ float  g_hR2[HW_];                 // of R^2
__device__ float2 g_AB[HW_];                  // (h,v): a, b
__device__ float  g_SL[HW_];                  // (h,w): patch sum of L
__device__ unsigned long long g_best[HW_];    // packed (enc(score) << 32) | (W-1-v)
__device__ float  g_scale;                    // fx * baseline

// ---------------- prep: pack float4 + horizontal 13-tap box sums + scale ----------------
__global__ void k_hbox(const float* __restrict__ L, const float* __restrict__ R,
                       const float* __restrict__ li,
                       const float* __restrict__ le,
                       const float* __restrict__ re) {
    int p = blockIdx.x * blockDim.x + threadIdx.x;
    if (p < HW_) {
        g_L4[p] = make_float4(L[p], L[p + HW_], L[p + 2*HW_], 0.f);
        g_R4[p] = make_float4(R[p], R[p + HW_], R[p + 2*HW_], 0.f);
        int x = p % W_;
        float hl = 0.f, r1 = 0.f, r2 = 0.f;
        #pragma unroll
        for (int dx = -6; dx <= 6; ++dx) {
            int xx = x + dx;
            if ((unsigned)xx < (unsigned)W_) {
                float l0 = L[p + dx], l1 = L[p + dx + HW_], l2 = L[p + dx + 2*HW_];
                float q0 = R[p + dx], q1 = R[p + dx + HW_], q2 = R[p + dx + 2*HW_];
                hl += l0 + l1 + l2;
                r1 += q0 + q1 + q2;
                r2 += q0*q0 + q1*q1 + q2*q2;
            }
        }
        g_hL[p] = hl; g_hR1[p] = r1; g_hR2[p] = r2;
    }
    if (p == 0) {
        float a[4][8];
        for (int i = 0; i < 4; ++i)
            for (int j = 0; j < 4; ++j) {
                a[i][j]     = le[i*4 + j];
                a[i][j + 4] = (i == j) ? 1.f : 0.f;
            }
        for (int c = 0; c < 4; ++c) {
            int piv = c; float mx = fabsf(a[c][c]);
            for (int r = c + 1; r < 4; ++r)
                if (fabsf(a[r][c]) > mx) { mx = fabsf(a[r][c]); piv = r; }
            if (piv != c)
                for (int j = 0; j < 8; ++j) { float tt = a[c][j]; a[c][j] = a[piv][j]; a[piv][j] = tt; }
            float inv = 1.f / a[c][c];
            for (int j = 0; j < 8; ++j) a[c][j] *= inv;
            for (int r = 0; r < 4; ++r) {
                if (r == c) continue;
                float f = a[r][c];
                for (int j = 0; j < 8; ++j) a[r][j] -= f * a[c][j];
            }
        }
        float t0 = 0.f, t1 = 0.f, t2 = 0.f;
        for (int k = 0; k < 4; ++k) {
            float ic = a[k][7];
            t0 += re[0*4 + k] * ic;
            t1 += re[1*4 + k] * ic;
            t2 += re[2*4 + k] * ic;
        }
        g_scale = li[0] * sqrtf(t0*t0 + t1*t1 + t2*t2);
    }
}

// ---------------- prep: vertical 13-tap + normalization terms ----------------
__global__ void k_vbox() {
    int p = blockIdx.x * blockDim.x + threadIdx.x;
    if (p >= HW_) return;
    int y = p / W_, x = p % W_;
    float sl = 0.f, s1 = 0.f, s2 = 0.f;
    #pragma unroll
    for (int dy = -6; dy <= 6; ++dy) {
        int yy = y + dy;
        if ((unsigned)yy < (unsigned)H_) {
            int q = yy * W_ + x;
            sl += g_hL[q]; s1 += g_hR1[q]; s2 += g_hR2[q];
        }
    }
    float var = fmaxf(s2 - s1 * s1 * INVD, 0.f);
    float a = 1.f / (sqrtf(var) + EPS_);
    g_AB[p] = make_float2(a, s1 * INVD * a);
    g_SL[p] = sl;
}

// ---------------- init g_best (keeps k_main in the profiled launch slot) -----
__global__ void k_init() {
    int p = blockIdx.x * blockDim.x + threadIdx.x;
    if (p < HW_) g_best[p] = 0ull;
}

// ---------------- main: float4 S-compute, 13-tap cross, circular R window ----
__global__ void __launch_bounds__(NT, 2) k_main() {
    extern __shared__ float4 sm4[];
    float4* rT = sm4;                               // NSLOT * W_ float4 rows
    float*  pl = (float*)(sm4 + NSLOT * W_);        // 16 V planes * PLW

    const int t    = threadIdx.x;
    const int half = t / W_;                        // 0 or 1
    const int x    = t % W_;
    const int h0   = blockIdx.y * HB;
    const int d0   = blockIdx.x * NDCTA + half * NDH;

    float* vpl = pl + (half * NDH) * PLW;           // this half's 8 V planes

    // zero planes once (pads + wrap gaps persist: wp positions are fixed per d)
    for (int i = t; i < 16 * PLW; i += NT) pl[i] = 0.f;

    // preload R row 0 into slot 0
    if (t < W_) {
        int y = h0 - 6;
        float4 v4 = make_float4(0.f, 0.f, 0.f, 0.f);
        if ((unsigned)y < (unsigned)H_) v4 = g_R4[y * W_ + t];
        rT[t] = v4;
    }

    // per-d constants
    int vv[NDH], wp[NDH];
    #pragma unroll
    for (int d = 0; d < NDH; ++d) {
        int dd = d0 + d;
        int v = x + dd; if (v >= W_) v -= W_;
        vv[d] = v;
        int c = W_ - dd;                            // wrap column
        wp[d] = (x < c) ? (6 + x) : (18 + x);       // seg1 [6,6+c), seg2 [18+c,338)
    }

    float SLr[HB];
    #pragma unroll
    for (int j = 0; j < HB; ++j) SLr[j] = g_SL[(h0 + j) * W_ + x];

    float bestS[HB]; int bestV[HB];
    #pragma unroll
    for (int j = 0; j < HB; ++j) { bestS[j] = -1e30f; bestV[j] = 0; }

    float V[NDH];
    #pragma unroll
    for (int d = 0; d < NDH; ++d) V[d] = 0.f;

    __syncthreads();   // row 0 + plane zeros visible

    #pragma unroll
    for (int s = 0; s < NSTEP; ++s) {
        // (a) prefetch R row s+1 into slot (s+1)%NSLOT
        //     slot held row s-14, last read at step s-1 (barrier-separated).
        if (s + 1 < NSTEP && t < W_) {
            int y = h0 - 6 + (s + 1);
            float4 v4 = make_float4(0.f, 0.f, 0.f, 0.f);
            if ((unsigned)y < (unsigned)H_) v4 = g_R4[y * W_ + t];
            rT[((s + 1) % NSLOT) * W_ + t] = v4;
        }

        // (b) incoming S at row s (one LDG.128 + 8x LDS.128)
        {
            int y = h0 - 6 + s;
            float4 lv = make_float4(0.f, 0.f, 0.f, 0.f);
            if ((unsigned)y < (unsigned)H_) lv = g_L4[y * W_ + x];
            const float4* rs = rT + (s % NSLOT) * W_;
            #pragma unroll
            for (int d = 0; d < NDH; ++d) {
                float4 rv = rs[vv[d]];
                V[d] += lv.x * rv.x + lv.y * rv.y + lv.z * rv.z;
            }
        }
        // (c) outgoing S at row s-13 (recomputed)
        if (s >= 13) {
            int y = h0 - 6 + (s - 13);
            float4 lv = make_float4(0.f, 0.f, 0.f, 0.f);
            if ((unsigned)y < (unsigned)H_) lv = g_L4[y * W_ + x];
            const float4* rs = rT + ((s - 13) % NSLOT) * W_;
            #pragma unroll
            for (int d = 0; d < NDH; ++d) {
                float4 rv = rs[vv[d]];
                V[d] -= lv.x * rv.x + lv.y * rv.y + lv.z * rv.z;
            }
        }

        // (d) output row h = h0 + s - 12 (V spans image rows [h-6, h+6])
        const int hh = s - 12;                      // compile-time
        if (hh >= 0) {
            #pragma unroll
            for (int d = 0; d < NDH; ++d)
                vpl[d * PLW + wp[d]] = V[d];
            float2 ABr[NDH];
            #pragma unroll
            for (int d = 0; d < NDH; ++d)
                ABr[d] = g_AB[(h0 + hh) * W_ + vv[d]];
            __syncthreads();                        // bar1: V stores (+prefetch) visible
            #pragma unroll
            for (int d = 0; d < NDH; ++d) {
                const float* q = &vpl[d * PLW + wp[d] - 6];
                float cr = q[0] + q[1] + q[2] + q[3] + q[4] + q[5] + q[6]
                         + q[7] + q[8] + q[9] + q[10] + q[11] + q[12];
                float sc = cr * ABr[d].x - SLr[hh] * ABr[d].y;
                if (sc > bestS[hh]) { bestS[hh] = sc; bestV[hh] = vv[d]; }
            }
            __syncthreads();                        // bar2: V planes reusable next row
        } else {
            __syncthreads();                        // prefetch visibility
        }
    }

    // one packed atomicMax per output pixel per (CTA, half)
    #pragma unroll
    for (int j = 0; j < HB; ++j) {
        unsigned eb = __float_as_uint(bestS[j]);
        eb = (eb & 0x80000000u) ? ~eb : (eb | 0x80000000u);   // order-preserving
        unsigned long long u = ((unsigned long long)eb << 32)
                             | (unsigned)(W_ - 1 - bestV[j]); // ties -> smallest v
        atomicMax(&g_best[(h0 + j) * W_ + x], u);
    }
}

// ---------------- depth ----------------
__global__ void k_depth(float* __restrict__ out) {
    int p = blockIdx.x * blockDim.x + threadIdx.x;
    if (p >= HW_) return;
    unsigned long long u = g_best[p];
    int bv = W_ - 1 - (int)(u & 0xFFFFFFFFull);
    int w = p % W_;
    float disp = fabsf((float)bv - (float)w);
    disp = fmaxf(disp, 0.001f);
    out[p] = g_scale / disp;
}

// ---------------- launch ----------------
extern "C" void kernel_launch(void* const* d_in, const int* in_sizes, int n_in,
                              void* d_out, int out_size) {
    const float* L  = (const float*)d_in[0];
    const float* R  = (const float*)d_in[1];
    const float* li = (const float*)d_in[2];
    const float* le = (const float*)d_in[4];
    const float* re = (const float*)d_in[5];

    const int smemBytes = NSLOT * W_ * 16 + 16 * PLW * 4;   // 76,800 + 22,016 = 98,816 B
    cudaFuncSetAttribute(k_main, cudaFuncAttributeMaxDynamicSharedMemorySize, smemBytes);

    k_hbox<<<(HW_ + 255) / 256, 256>>>(L, R, li, le, re);
    k_vbox<<<(HW_ + 255) / 256, 256>>>();
    k_init<<<(HW_ + 255) / 256, 256>>>();        // keeps k_main in profiled slot

    dim3 grid(GRIDX, NHB);
    k_main<<<grid, NT, smemBytes>>>();

    k_depth<<<(HW_ + 255) / 256, 256>>>((float*)d_out);
}

// round 13
// speedup vs baseline: 1.0946x; 1.0946x over previous
#include <cuda_runtime.h>
#include <math.h>

#define H_    192
#define W_    320
#define HW_   (H_*W_)
#define EPS_  1e-5f
#define INVD  (1.0f/507.0f)

#define HB     16               // output rows per CTA
#define NHB    12               // 192/16
#define NDH    8                // d's per half
#define NDCTA  16               // d's per CTA
#define GRIDX  20               // 20*16 = 320 d values
#define NT     640              // threads: (half, x)
#define NSTEP  28               // HB+12 row steps
#define NSLOT  17               // circular R-row window (prefetch distance 2)
#define PADW   328              // padded row: cols 320..326 replicate 0..6
#define PLW    344              // V plane width: 6+320+12(gap)+6

// ---------------- device scratch ----------------
__device__ float  g_hL[HW_];
__device__ float  g_hR1[HW_];
__device__ float  g_hR2[HW_];
__device__ float2 g_AB[HW_];                  // (h,v): a, b
__device__ float  g_SL[HW_];                  // (h,w): patch sum of L
__device__ unsigned long long g_best[HW_];    // packed (enc(score) << 32) | (W-1-v)
__device__ float  g_scale;

// ---------------- prep: horizontal 13-tap box sums + scale ----------------
__global__ void k_hbox(const float* __restrict__ L, const float* __restrict__ R,
                       const float* __restrict__ li,
                       const float* __restrict__ le,
                       const float* __restrict__ re) {
    int p = blockIdx.x * blockDim.x + threadIdx.x;
    if (p < HW_) {
        int x = p % W_;
        float hl = 0.f, r1 = 0.f, r2 = 0.f;
        #pragma unroll
        for (int dx = -6; dx <= 6; ++dx) {
            int xx = x + dx;
            if ((unsigned)xx < (unsigned)W_) {
                float l0 = L[p + dx], l1 = L[p + dx + HW_], l2 = L[p + dx + 2*HW_];
                float q0 = R[p + dx], q1 = R[p + dx + HW_], q2 = R[p + dx + 2*HW_];
                hl += l0 + l1 + l2;
                r1 += q0 + q1 + q2;
                r2 += q0*q0 + q1*q1 + q2*q2;
            }
        }
        g_hL[p] = hl; g_hR1[p] = r1; g_hR2[p] = r2;
    }
    if (p == 0) {
        float a[4][8];
        for (int i = 0; i < 4; ++i)
            for (int j = 0; j < 4; ++j) {
                a[i][j]     = le[i*4 + j];
                a[i][j + 4] = (i == j) ? 1.f : 0.f;
            }
        for (int c = 0; c < 4; ++c) {
            int piv = c; float mx = fabsf(a[c][c]);
            for (int r = c + 1; r < 4; ++r)
                if (fabsf(a[r][c]) > mx) { mx = fabsf(a[r][c]); piv = r; }
            if (piv != c)
                for (int j = 0; j < 8; ++j) { float tt = a[c][j]; a[c][j] = a[piv][j]; a[piv][j] = tt; }
            float inv = 1.f / a[c][c];
            for (int j = 0; j < 8; ++j) a[c][j] *= inv;
            for (int r = 0; r < 4; ++r) {
                if (r == c) continue;
                float f = a[r][c];
                for (int j = 0; j < 8; ++j) a[r][j] -= f * a[c][j];
            }
        }
        float t0 = 0.f, t1 = 0.f, t2 = 0.f;
        for (int k = 0; k < 4; ++k) {
            float ic = a[k][7];
            t0 += re[0*4 + k] * ic;
            t1 += re[1*4 + k] * ic;
            t2 += re[2*4 + k] * ic;
        }
        g_scale = li[0] * sqrtf(t0*t0 + t1*t1 + t2*t2);
    }
}

// ---------------- prep: vertical 13-tap + normalization terms ----------------
__global__ void k_vbox() {
    int p = blockIdx.x * blockDim.x + threadIdx.x;
    if (p >= HW_) return;
    int y = p / W_, x = p % W_;
    float sl = 0.f, s1 = 0.f, s2 = 0.f;
    #pragma unroll
    for (int dy = -6; dy <= 6; ++dy) {
        int yy = y + dy;
        if ((unsigned)yy < (unsigned)H_) {
            int q = yy * W_ + x;
            sl += g_hL[q]; s1 += g_hR1[q]; s2 += g_hR2[q];
        }
    }
    float var = fmaxf(s2 - s1 * s1 * INVD, 0.f);
    float a = 1.f / (sqrtf(var) + EPS_);
    g_AB[p] = make_float2(a, s1 * INVD * a);
    g_SL[p] = sl;
}

// ---------------- init g_best (keeps k_main in the profiled launch slot) -----
__global__ void k_init() {
    int p = blockIdx.x * blockDim.x + threadIdx.x;
    if (p < HW_) g_best[p] = 0ull;
}

// helper: cooperative load of R row y into padded slot (cols 320..326 = 0..6)
__device__ __forceinline__ void load_r_row(float* dst, const float* __restrict__ R,
                                           int y, int t) {
    bool valid = ((unsigned)y < (unsigned)H_);
    const float* base = R + y * W_;
    for (int i = t; i < 3 * PADW; i += NT) {
        int ch  = i / PADW;
        int col = i - ch * PADW;
        int c2  = (col < W_) ? col : col - W_;
        dst[i] = valid ? base[ch * HW_ + c2] : 0.f;
    }
}

// ---------------- main: padded-window gathers, 22 bars, L prefetch ----------
__global__ void __launch_bounds__(NT, 2) k_main(const float* __restrict__ L,
                                                const float* __restrict__ R) {
    extern __shared__ float sm[];
    float* rT = sm;                             // NSLOT slots * (3*PADW)
    float* pl = sm + NSLOT * 3 * PADW;          // 32 V planes * PLW

    const int t    = threadIdx.x;
    const int half = t / W_;
    const int x    = t % W_;
    const int h0   = blockIdx.y * HB;
    const int d0   = blockIdx.x * NDCTA + half * NDH;

    float* vpl = pl + (half * 2 * NDH) * PLW;   // this half's 2 parity sets

    // zero planes once (pads + fixed wrap gaps)
    for (int i = t; i < 32 * PLW; i += NT) pl[i] = 0.f;

    // preload R rows 0 and 1 (steps 0,1); prefetch distance 2 thereafter
    load_r_row(rT + 0 * (3*PADW), R, h0 - 6 + 0, t);
    load_r_row(rT + 1 * (3*PADW), R, h0 - 6 + 1, t);

    // per-thread constants
    int vbase = x + d0; if (vbase >= W_) vbase -= W_;   // gather base (padded idx)
    int vv[NDH], wp[NDH];
    #pragma unroll
    for (int d = 0; d < NDH; ++d) {
        int vp = vbase + d;
        vv[d] = (vp >= W_) ? vp - W_ : vp;              // true v (AB / bestV)
        int c = W_ - (d0 + d);                          // wrap column
        wp[d] = (x < c) ? (6 + x) : (18 + x);
    }

    float bestS[HB]; int bestV[HB];
    #pragma unroll
    for (int j = 0; j < HB; ++j) { bestS[j] = -1e30f; bestV[j] = 0; }

    float V[NDH];
    #pragma unroll
    for (int d = 0; d < NDH; ++d) V[d] = 0.f;

    // incoming L row for step 0
    float lc0 = 0.f, lc1 = 0.f, lc2 = 0.f;
    {
        int y = h0 - 6;
        if ((unsigned)y < (unsigned)H_) {
            int p = y * W_ + x;
            lc0 = L[p]; lc1 = L[p + HW_]; lc2 = L[p + 2*HW_];
        }
    }

    __syncthreads();   // rows 0,1 + plane zeros visible

    #pragma unroll
    for (int s = 0; s < NSTEP; ++s) {
        // (a) prefetch R row s+2 (read at step s+2; a bar always intervenes)
        if (s + 2 < NSTEP)
            load_r_row(rT + ((s + 2) % NSLOT) * (3*PADW), R, h0 - 6 + s + 2, t);

        // (b) prefetch next step's incoming L row
        float ln0 = 0.f, ln1 = 0.f, ln2 = 0.f;
        if (s + 1 < NSTEP) {
            int y = h0 - 6 + s + 1;
            if ((unsigned)y < (unsigned)H_) {
                int p = y * W_ + x;
                ln0 = L[p]; ln1 = L[p + HW_]; ln2 = L[p + 2*HW_];
            }
        }

        // (c) incoming S at row s: one base, immediate-offset gathers
        {
            const float* rs = rT + (s % NSLOT) * (3*PADW) + vbase;
            #pragma unroll
            for (int d = 0; d < NDH; ++d)
                V[d] += lc0 * rs[d] + lc1 * rs[PADW + d] + lc2 * rs[2*PADW + d];
        }
        // (d) outgoing S at row s-13 (recompute; L row is L1-resident)
        if (s >= 13) {
            int y = h0 - 6 + s - 13;
            float lo0 = 0.f, lo1 = 0.f, lo2 = 0.f;
            if ((unsigned)y < (unsigned)H_) {
                int p = y * W_ + x;
                lo0 = L[p]; lo1 = L[p + HW_]; lo2 = L[p + 2*HW_];
            }
            const float* rs = rT + ((s - 13) % NSLOT) * (3*PADW) + vbase;
            #pragma unroll
            for (int d = 0; d < NDH; ++d)
                V[d] -= lo0 * rs[d] + lo1 * rs[PADW + d] + lo2 * rs[2*PADW + d];
        }

        // (e) output row h = h0 + s - 12
        const int hh = s - 12;                    // compile-time
        if (hh >= 0) {
            float* vb = vpl + ((hh & 1) * NDH) * PLW;
            #pragma unroll
            for (int d = 0; d < NDH; ++d)
                vb[d * PLW + wp[d]] = V[d];
            // prefetch AB + SL for this row (latency spans the barrier)
            float2 ABr[NDH];
            #pragma unroll
            for (int d = 0; d < NDH; ++d)
                ABr[d] = g_AB[(h0 + hh) * W_ + vv[d]];
            float slr = g_SL[(h0 + hh) * W_ + x];
            __syncthreads();                      // bar: V stores (+window) visible
            #pragma unroll
            for (int d = 0; d < NDH; ++d) {
                const float* q = vb + d * PLW + wp[d] - 6;
                float cr = q[0] + q[1] + q[2] + q[3] + q[4] + q[5] + q[6]
                         + q[7] + q[8] + q[9] + q[10] + q[11] + q[12];
                float sc = cr * ABr[d].x - slr * ABr[d].y;
                if (sc > bestS[hh]) { bestS[hh] = sc; bestV[hh] = vv[d]; }
            }
        } else if (s & 1) {
            __syncthreads();                      // warmup: bar on odd steps only
        }

        lc0 = ln0; lc1 = ln1; lc2 = ln2;          // rotate L prefetch
    }

    // one packed atomicMax per output pixel per (CTA, half)
    #pragma unroll
    for (int j = 0; j < HB; ++j) {
        unsigned eb = __float_as_uint(bestS[j]);
        eb = (eb & 0x80000000u) ? ~eb : (eb | 0x80000000u);   // order-preserving
        unsigned long long u = ((unsigned long long)eb << 32)
                             | (unsigned)(W_ - 1 - bestV[j]); // ties -> smallest v
        atomicMax(&g_best[(h0 + j) * W_ + x], u);
    }
}

// ---------------- depth ----------------
__global__ void k_depth(float* __restrict__ out) {
    int p = blockIdx.x * blockDim.x + threadIdx.x;
    if (p >= HW_) return;
    unsigned long long u = g_best[p];
    int bv = W_ - 1 - (int)(u & 0xFFFFFFFFull);
    int w = p % W_;
    float disp = fabsf((float)bv - (float)w);
    disp = fmaxf(disp, 0.001f);
    out[p] = g_scale / disp;
}

// ---------------- launch ----------------
extern "C" void kernel_launch(void* const* d_in, const int* in_sizes, int n_in,
                              void* d_out, int out_size) {
    const float* L  = (const float*)d_in[0];
    const float* R  = (const float*)d_in[1];
    const float* li = (const float*)d_in[2];
    const float* le = (const float*)d_in[4];
    const float* re = (const float*)d_in[5];

    const int smemBytes = (NSLOT * 3 * PADW + 32 * PLW) * 4;   // 66,912+44,032=110,944 B
    cudaFuncSetAttribute(k_main, cudaFuncAttributeMaxDynamicSharedMemorySize, smemBytes);

    k_hbox<<<(HW_ + 255) / 256, 256>>>(L, R, li, le, re);
    k_vbox<<<(HW_ + 255) / 256, 256>>>();
    k_init<<<(HW_ + 255) / 256, 256>>>();        // keeps k_main in profiled slot

    dim3 grid(GRIDX, NHB);
    k_main<<<grid, NT, smemBytes>>>(L, R);

    k_depth<<<(HW_ + 255) / 256, 256>>>((float*)d_out);
}

// round 14
// speedup vs baseline: 1.3698x; 1.2515x over previous
#include <cuda_runtime.h>
#include <math.h>

#define H_    192
#define W_    320
#define HW_   (H_*W_)
#define EPS_  1e-5f
#define INVD  (1.0f/507.0f)

#define HB     16               // output rows per CTA
#define NHB    12               // 192/16
#define NDH    8                // d's per CTA
#define GRIDX  40               // 40*8 = 320 d values
#define NT     320              // one thread per column
#define NSTEP  28               // HB+12 row steps
#define NSLOT  17               // circular R-row window (prefetch distance 2)
#define PADW   328              // padded row: cols 320..327 replicate 0..7
#define PLROW  321              // prefix row: slot0 = 0 sentinel, lanes at 1+x
#define TWROW  11               // 10 warp totals + zero slot [10]

// ---------------- device scratch ----------------
__device__ float  g_hL[HW_];
__device__ float  g_hR1[HW_];
__device__ float  g_hR2[HW_];
__device__ float2 g_AB[HW_];                  // (h,v): a, b
__device__ float  g_SL[HW_];                  // (h,w): patch sum of L
__device__ unsigned long long g_best[HW_];    // packed (enc(score) << 32) | (W-1-v)
__device__ float  g_scale;

// ---------------- prep: horizontal 13-tap box sums + scale ----------------
__global__ void k_hbox(const float* __restrict__ L, const float* __restrict__ R,
                       const float* __restrict__ li,
                       const float* __restrict__ le,
                       const float* __restrict__ re) {
    int p = blockIdx.x * blockDim.x + threadIdx.x;
    if (p < HW_) {
        int x = p % W_;
        float hl = 0.f, r1 = 0.f, r2 = 0.f;
        #pragma unroll
        for (int dx = -6; dx <= 6; ++dx) {
            int xx = x + dx;
            if ((unsigned)xx < (unsigned)W_) {
                float l0 = L[p + dx], l1 = L[p + dx + HW_], l2 = L[p + dx + 2*HW_];
                float q0 = R[p + dx], q1 = R[p + dx + HW_], q2 = R[p + dx + 2*HW_];
                hl += l0 + l1 + l2;
                r1 += q0 + q1 + q2;
                r2 += q0*q0 + q1*q1 + q2*q2;
            }
        }
        g_hL[p] = hl; g_hR1[p] = r1; g_hR2[p] = r2;
    }
    if (p == 0) {
        float a[4][8];
        for (int i = 0; i < 4; ++i)
            for (int j = 0; j < 4; ++j) {
                a[i][j]     = le[i*4 + j];
                a[i][j + 4] = (i == j) ? 1.f : 0.f;
            }
        for (int c = 0; c < 4; ++c) {
            int piv = c; float mx = fabsf(a[c][c]);
            for (int r = c + 1; r < 4; ++r)
                if (fabsf(a[r][c]) > mx) { mx = fabsf(a[r][c]); piv = r; }
            if (piv != c)
                for (int j = 0; j < 8; ++j) { float tt = a[c][j]; a[c][j] = a[piv][j]; a[piv][j] = tt; }
            float inv = 1.f / a[c][c];
            for (int j = 0; j < 8; ++j) a[c][j] *= inv;
            for (int r = 0; r < 4; ++r) {
                if (r == c) continue;
                float f = a[r][c];
                for (int j = 0; j < 8; ++j) a[r][j] -= f * a[c][j];
            }
        }
        float t0 = 0.f, t1 = 0.f, t2 = 0.f;
        for (int k = 0; k < 4; ++k) {
            float ic = a[k][7];
            t0 += re[0*4 + k] * ic;
            t1 += re[1*4 + k] * ic;
            t2 += re[2*4 + k] * ic;
        }
        g_scale = li[0] * sqrtf(t0*t0 + t1*t1 + t2*t2);
    }
}

// ---------------- prep: vertical 13-tap + normalization terms ----------------
__global__ void k_vbox() {
    int p = blockIdx.x * blockDim.x + threadIdx.x;
    if (p >= HW_) return;
    int y = p / W_, x = p % W_;
    float sl = 0.f, s1 = 0.f, s2 = 0.f;
    #pragma unroll
    for (int dy = -6; dy <= 6; ++dy) {
        int yy = y + dy;
        if ((unsigned)yy < (unsigned)H_) {
            int q = yy * W_ + x;
            sl += g_hL[q]; s1 += g_hR1[q]; s2 += g_hR2[q];
        }
    }
    float var = fmaxf(s2 - s1 * s1 * INVD, 0.f);
    float a = 1.f / (sqrtf(var) + EPS_);
    g_AB[p] = make_float2(a, s1 * INVD * a);
    g_SL[p] = sl;
}

// ---------------- init g_best (keeps k_main in the profiled launch slot) -----
__global__ void k_init() {
    int p = blockIdx.x * blockDim.x + threadIdx.x;
    if (p < HW_) g_best[p] = 0ull;
}

// helper: cooperative load of R row y into padded slot (cols 320..327 = 0..7)
__device__ __forceinline__ void load_r_row(float* dst, const float* __restrict__ R,
                                           int y, int t) {
    bool valid = ((unsigned)y < (unsigned)H_);
    const float* base = R + y * W_;
    #pragma unroll
    for (int i = t; i < 3 * PADW; i += NT) {
        int ch  = i / PADW;
        int col = i - ch * PADW;
        int c2  = (col < W_) ? col : col - W_;
        dst[i] = valid ? base[ch * HW_ + c2] : 0.f;
    }
}

// ---------------- main: warp-prefix cross, no spills, RED.MAX merge ----------
__global__ void __launch_bounds__(NT, 2) k_main(const float* __restrict__ L,
                                                const float* __restrict__ R) {
    extern __shared__ float sm[];
    float* rT = sm;                              // NSLOT * 3*PADW
    float* Pl = sm + NSLOT * 3 * PADW;           // 2 parity * NDH * PLROW
    float* Tw = Pl + 2 * NDH * PLROW;            // 2 parity * NDH * TWROW

    const int x    = threadIdx.x;
    const int lane = x & 31;
    const int warp = x >> 5;                     // 0..9
    const int h0   = blockIdx.y * HB;
    const int d0   = blockIdx.x * NDH;

    // zero sentinels: Pl[row][0] = 0, Tw[row][10] = 0 (written once)
    if (x < 2 * NDH) {
        Pl[x * PLROW] = 0.f;
        Tw[x * TWROW + 10] = 0.f;
    }

    // preload R rows for steps 0,1; prefetch distance 2 thereafter
    load_r_row(rT,            R, h0 - 6,     x);
    load_r_row(rT + 3*PADW,   R, h0 - 5,     x);

    // per-d constants: true v, clamped-window prefix indices, warp-total index
    int vbase = x + d0; if (vbase >= W_) vbase -= W_;
    int vv[NDH], aidx[NDH], bidx[NDH], tidx[NDH];
    #pragma unroll
    for (int d = 0; d < NDH; ++d) {
        int vp = vbase + d;
        vv[d] = (vp >= W_) ? vp - W_ : vp;
        int c = W_ - (d0 + d);                   // wrap column (lane c starts seg2)
        int lo = (x < c) ? 0 : c;
        int hi = (x < c) ? (c - 1) : (W_ - 1);
        int a  = min(x + 6, hi);                 // last lane in window
        int b  = max(x - 6, lo) - 1;             // lane before window (-1 -> 0)
        aidx[d] = a + 1;                         // +1: slot 0 is the zero sentinel
        bidx[d] = b + 1;
        int aw = a >> 5;
        int bw = ((b < 0) ? 0 : b) >> 5;
        tidx[d] = (aw != bw) ? bw : 10;          // neighbor warp total or zero slot
    }

    float V[NDH];
    #pragma unroll
    for (int d = 0; d < NDH; ++d) V[d] = 0.f;

    // incoming L row for step 0
    float lc0 = 0.f, lc1 = 0.f, lc2 = 0.f;
    {
        int y = h0 - 6;
        if ((unsigned)y < (unsigned)H_) {
            int p = y * W_ + x;
            lc0 = L[p]; lc1 = L[p + HW_]; lc2 = L[p + 2*HW_];
        }
    }

    __syncthreads();   // rows 0,1 + sentinels visible

    #pragma unroll
    for (int s = 0; s < NSTEP; ++s) {
        // (a) prefetch R row s+2 (slot conflicts only possible from s>=15,
        //     where every step has an output barrier)
        if (s + 2 < NSTEP)
            load_r_row(rT + ((s + 2) % NSLOT) * (3*PADW), R, h0 - 6 + s + 2, x);

        // (b) prefetch next step's incoming L row
        float ln0 = 0.f, ln1 = 0.f, ln2 = 0.f;
        if (s + 1 < NSTEP) {
            int y = h0 - 6 + s + 1;
            if ((unsigned)y < (unsigned)H_) {
                int p = y * W_ + x;
                ln0 = L[p]; ln1 = L[p + HW_]; ln2 = L[p + 2*HW_];
            }
        }

        // (c) incoming S at row s
        {
            const float* rs = rT + (s % NSLOT) * (3*PADW) + vbase;
            #pragma unroll
            for (int d = 0; d < NDH; ++d)
                V[d] += lc0 * rs[d] + lc1 * rs[PADW + d] + lc2 * rs[2*PADW + d];
        }
        // (d) outgoing S at row s-13 (recompute)
        if (s >= 13) {
            int y = h0 - 6 + s - 13;
            float lo0 = 0.f, lo1 = 0.f, lo2 = 0.f;
            if ((unsigned)y < (unsigned)H_) {
                int p = y * W_ + x;
                lo0 = L[p]; lo1 = L[p + HW_]; lo2 = L[p + 2*HW_];
            }
            const float* rs = rT + ((s - 13) % NSLOT) * (3*PADW) + vbase;
            #pragma unroll
            for (int d = 0; d < NDH; ++d)
                V[d] -= lo0 * rs[d] + lo1 * rs[PADW + d] + lo2 * rs[2*PADW + d];
        }

        // (e) output row h = h0 + s - 12
        const int hh = s - 12;                   // compile-time
        if (hh >= 0) {
            const int par = hh & 1;
            float* plb = Pl + par * NDH * PLROW;
            float* twb = Tw + par * NDH * TWROW;

            // prefetch AB + SL (latency spans prefix + barrier)
            float2 ABr[NDH];
            #pragma unroll
            for (int d = 0; d < NDH; ++d)
                ABr[d] = g_AB[(h0 + hh) * W_ + vv[d]];
            float slr = g_SL[(h0 + hh) * W_ + x];

            // warp-inclusive prefix of V per d; publish prefix + warp total
            #pragma unroll
            for (int d = 0; d < NDH; ++d) {
                float p = V[d], n;
                n = __shfl_up_sync(0xffffffffu, p, 1);  if (lane >= 1)  p += n;
                n = __shfl_up_sync(0xffffffffu, p, 2);  if (lane >= 2)  p += n;
                n = __shfl_up_sync(0xffffffffu, p, 4);  if (lane >= 4)  p += n;
                n = __shfl_up_sync(0xffffffffu, p, 8);  if (lane >= 8)  p += n;
                n = __shfl_up_sync(0xffffffffu, p, 16); if (lane >= 16) p += n;
                plb[d * PLROW + 1 + x] = p;
                float tot = __shfl_sync(0xffffffffu, p, 31);
                if (lane == 0) twb[d * TWROW + warp] = tot;
            }
            __syncthreads();                     // prefixes + R-window visible

            float bS = -1e30f; int bV = 0;
            #pragma unroll
            for (int d = 0; d < NDH; ++d) {
                const float* pr = plb + d * PLROW;
                float cr = pr[aidx[d]] - pr[bidx[d]] + twb[d * TWROW + tidx[d]];
                float sc = cr * ABr[d].x - slr * ABr[d].y;
                if (sc > bS) { bS = sc; bV = vv[d]; }
            }
            // fire-and-forget packed max (RED.MAX.U64): ties -> smallest v
            unsigned eb = __float_as_uint(bS);
            eb = (eb & 0x80000000u) ? ~eb : (eb | 0x80000000u);
            unsigned long long u = ((unsigned long long)eb << 32)
                                 | (unsigned)(W_ - 1 - bV);
            atomicMax(&g_best[(h0 + hh) * W_ + x], u);
        } else if (s & 1) {
            __syncthreads();                     // warmup: prefetch visibility
        }

        lc0 = ln0; lc1 = ln1; lc2 = ln2;         // rotate L prefetch
    }
}

// ---------------- depth ----------------
__global__ void k_depth(float* __restrict__ out) {
    int p = blockIdx.x * blockDim.x + threadIdx.x;
    if (p >= HW_) return;
    unsigned long long u = g_best[p];
    int bv = W_ - 1 - (int)(u & 0xFFFFFFFFull);
    int w = p % W_;
    float disp = fabsf((float)bv - (float)w);
    disp = fmaxf(disp, 0.001f);
    out[p] = g_scale / disp;
}

// ---------------- launch ----------------
extern "C" void kernel_launch(void* const* d_in, const int* in_sizes, int n_in,
                              void* d_out, int out_size) {
    const float* L  = (const float*)d_in[0];
    const float* R  = (const float*)d_in[1];
    const float* li = (const float*)d_in[2];
    const float* le = (const float*)d_in[4];
    const float* re = (const float*)d_in[5];

    const int smemBytes = (NSLOT * 3 * PADW + 2 * NDH * PLROW + 2 * NDH * TWROW) * 4;
    // 66,912 + 20,544 + 704 = 88,160 B  -> 2 CTAs/SM
    cudaFuncSetAttribute(k_main, cudaFuncAttributeMaxDynamicSharedMemorySize, smemBytes);

    k_hbox<<<(HW_ + 255) / 256, 256>>>(L, R, li, le, re);
    k_vbox<<<(HW_ + 255) / 256, 256>>>();
    k_init<<<(HW_ + 255) / 256, 256>>>();        // keeps k_main in profiled slot

    dim3 grid(GRIDX, NHB);
    k_main<<<grid, NT, smemBytes>>>(L, R);

    k_depth<<<(HW_ + 255) / 256, 256>>>((float*)d_out);
}